// round 14
// baseline (speedup 1.0000x reference)
#include <cuda_runtime.h>
#include <cuda_fp16.h>

#define NN 100000
#define NE 1200000
#define DD 64
#define ADJ_STRIDE 32
#define OVF_CAP 8192
#define NTF 3125                // 100000/32 fused tiles (exact)
#define NBUCK 33                // degree buckets 0..32
#define SW128(o) ((o) ^ ((((o) >> 3)) & 0x70))

typedef unsigned long long u64;

// Scratch (device globals — no allocation allowed)
__device__ __half g_Hh  [NN * DD];        // layer-1 gather source (feats*nout)
__device__ __half g_H2h [NN * DD];        // layer-2 gather source
__device__ __half g_Wt[2][DD * DD];       // pre-transposed fp16 weights [c*64+k]
__device__ int   g_degout[NN];
__device__ int   g_cnt[NN];
__device__ float g_nout[NN];
__device__ float g_nin[NN];
__device__ int   g_adj[NN * ADJ_STRIDE];
__device__ int   g_ovf[OVF_CAP];
__device__ int   g_ovf_cnt;
__device__ int   g_bucket[NBUCK];         // degree histogram
__device__ int   g_cursor[NBUCK];         // bucket allocation cursors
__device__ int   g_perm[NN];              // degree-sorted node order

// ---------------------------------------------------------------------------
// zero counters + pre-transpose weights (merged: saves a launch)
__global__ void k_zero(const float* __restrict__ W1, const float* __restrict__ W2) {
    int i = blockIdx.x * blockDim.x + threadIdx.x;
    if (i < NN) { g_degout[i] = 0; g_cnt[i] = 0; }
    if (i == 0) g_ovf_cnt = 0;
    if (i < NBUCK) g_bucket[i] = 0;
    if (i < 2 * DD * DD) {
        int l = i >> 12;
        int r = i & 4095;
        int c = r >> 6, k = r & 63;
        const float* W = l ? W2 : W1;
        g_Wt[l][c * 64 + k] = __float2half_rn(W[k * 64 + c]);
    }
}

// 4 edges per thread (int4 loads) for atomic-latency MLP.
__global__ void k_build(const int4* __restrict__ src4, const int4* __restrict__ dst4) {
    int e4 = blockIdx.x * blockDim.x + threadIdx.x;
    if (e4 >= NE / 4) return;
    int4 s = src4[e4];
    int4 d = dst4[e4];
    atomicAdd(&g_degout[s.x], 1);
    atomicAdd(&g_degout[s.y], 1);
    atomicAdd(&g_degout[s.z], 1);
    atomicAdd(&g_degout[s.w], 1);
    int c0 = atomicAdd(&g_cnt[d.x], 1);
    int c1 = atomicAdd(&g_cnt[d.y], 1);
    int c2 = atomicAdd(&g_cnt[d.z], 1);
    int c3 = atomicAdd(&g_cnt[d.w], 1);
    int base = e4 * 4;
    if (c0 < ADJ_STRIDE) g_adj[d.x * ADJ_STRIDE + c0] = s.x;
    else { int o = atomicAdd(&g_ovf_cnt, 1); if (o < OVF_CAP) g_ovf[o] = base; }
    if (c1 < ADJ_STRIDE) g_adj[d.y * ADJ_STRIDE + c1] = s.y;
    else { int o = atomicAdd(&g_ovf_cnt, 1); if (o < OVF_CAP) g_ovf[o] = base + 1; }
    if (c2 < ADJ_STRIDE) g_adj[d.z * ADJ_STRIDE + c2] = s.z;
    else { int o = atomicAdd(&g_ovf_cnt, 1); if (o < OVF_CAP) g_ovf[o] = base + 2; }
    if (c3 < ADJ_STRIDE) g_adj[d.w * ADJ_STRIDE + c3] = s.w;
    else { int o = atomicAdd(&g_ovf_cnt, 1); if (o < OVF_CAP) g_ovf[o] = base + 3; }
}

// norms + degree histogram
__global__ void k_norm() {
    int i = blockIdx.x * blockDim.x + threadIdx.x;
    if (i < NN) {
        int cin = g_cnt[i];
        g_nout[i] = rsqrtf(fmaxf((float)g_degout[i], 1.0f));
        g_nin[i]  = rsqrtf(fmaxf((float)cin, 1.0f));
        int b = cin < 32 ? cin : 32;
        atomicAdd(&g_bucket[b], 1);
    }
}

// exclusive scan of 33 buckets (tiny, 1 thread)
__global__ void k_scan() {
    if (threadIdx.x == 0) {
        int run = 0;
        for (int b = 0; b < NBUCK; b++) {
            g_cursor[b] = run;
            run += g_bucket[b];
        }
    }
}

// degree-sorted permutation (block-aggregated counting sort scatter)
__global__ void __launch_bounds__(256) k_perm() {
    __shared__ int sh_cnt[NBUCK], sh_base[NBUCK];
    int t = threadIdx.x;
    int i = blockIdx.x * 256 + t;
    if (t < NBUCK) sh_cnt[t] = 0;
    __syncthreads();
    int b = 0, mypos = 0;
    if (i < NN) {
        int cin = g_cnt[i];
        b = cin < 32 ? cin : 32;
        mypos = atomicAdd(&sh_cnt[b], 1);
    }
    __syncthreads();
    if (t < NBUCK) sh_base[t] = atomicAdd(&g_cursor[t], sh_cnt[t]);
    __syncthreads();
    if (i < NN) g_perm[sh_base[b] + mypos] = i;
}

// Pure stream: Hh = half(feats * nout[row]); one 64-float row per thread? No:
// 4 consecutive float4 (one quarter-row... actually 4 chunks = same row) per thread.
__global__ void k_scale(const float4* __restrict__ feats) {
    int q = blockIdx.x * blockDim.x + threadIdx.x;   // NN*4 quads
    if (q >= NN * 4) return;
    int t0 = q * 4;                                   // 4 float4s, same row
    float s = g_nout[t0 >> 4];
    float4 v0 = feats[t0];
    float4 v1 = feats[t0 + 1];
    float4 v2 = feats[t0 + 2];
    float4 v3 = feats[t0 + 3];
    __half2 a0 = __floats2half2_rn(v0.x * s, v0.y * s);
    __half2 a1 = __floats2half2_rn(v0.z * s, v0.w * s);
    __half2 a2 = __floats2half2_rn(v1.x * s, v1.y * s);
    __half2 a3 = __floats2half2_rn(v1.z * s, v1.w * s);
    __half2 b0 = __floats2half2_rn(v2.x * s, v2.y * s);
    __half2 b1 = __floats2half2_rn(v2.z * s, v2.w * s);
    __half2 b2 = __floats2half2_rn(v3.x * s, v3.y * s);
    __half2 b3 = __floats2half2_rn(v3.z * s, v3.w * s);
    uint4 u, w;
    u.x = *reinterpret_cast<unsigned*>(&a0);
    u.y = *reinterpret_cast<unsigned*>(&a1);
    u.z = *reinterpret_cast<unsigned*>(&a2);
    u.w = *reinterpret_cast<unsigned*>(&a3);
    w.x = *reinterpret_cast<unsigned*>(&b0);
    w.y = *reinterpret_cast<unsigned*>(&b1);
    w.z = *reinterpret_cast<unsigned*>(&b2);
    w.w = *reinterpret_cast<unsigned*>(&b3);
    reinterpret_cast<uint4*>(g_Hh)[q * 2]     = u;
    reinterpret_cast<uint4*>(g_Hh)[q * 2 + 1] = w;
}

// acc (8 floats) += 8 halves packed in uint4
__device__ __forceinline__ void acc8h(float4& a, float4& b, uint4 u) {
    float2 f0 = __half22float2(*reinterpret_cast<__half2*>(&u.x));
    float2 f1 = __half22float2(*reinterpret_cast<__half2*>(&u.y));
    float2 f2 = __half22float2(*reinterpret_cast<__half2*>(&u.z));
    float2 f3 = __half22float2(*reinterpret_cast<__half2*>(&u.w));
    a.x += f0.x; a.y += f0.y; a.z += f1.x; a.w += f1.y;
    b.x += f2.x; b.y += f2.y; b.z += f3.x; b.w += f3.y;
}
// pairwise fp16 add of two uint4s (4x HADD2)
__device__ __forceinline__ uint4 hadd2x4(uint4 a, uint4 b) {
    uint4 r;
    *reinterpret_cast<__half2*>(&r.x) = __hadd2(*reinterpret_cast<__half2*>(&a.x),
                                                *reinterpret_cast<__half2*>(&b.x));
    *reinterpret_cast<__half2*>(&r.y) = __hadd2(*reinterpret_cast<__half2*>(&a.y),
                                                *reinterpret_cast<__half2*>(&b.y));
    *reinterpret_cast<__half2*>(&r.z) = __hadd2(*reinterpret_cast<__half2*>(&a.z),
                                                *reinterpret_cast<__half2*>(&b.z));
    *reinterpret_cast<__half2*>(&r.w) = __hadd2(*reinterpret_cast<__half2*>(&a.w),
                                                *reinterpret_cast<__half2*>(&b.w));
    return r;
}

__device__ __forceinline__ unsigned smem_u32(const void* p) {
    unsigned a;
    asm("{ .reg .u64 t; cvta.to.shared.u64 t, %1; cvt.u32.u64 %0, t; }" : "=r"(a) : "l"(p));
    return a;
}
__device__ __forceinline__ void ldmx4(unsigned& r0, unsigned& r1, unsigned& r2,
                                      unsigned& r3, unsigned addr) {
    asm volatile("ldmatrix.sync.aligned.m8n8.x4.shared.b16 {%0,%1,%2,%3}, [%4];"
                 : "=r"(r0), "=r"(r1), "=r"(r2), "=r"(r3) : "r"(addr));
}
__device__ __forceinline__ void mma16816(float* d, unsigned a0, unsigned a1,
                                         unsigned a2, unsigned a3,
                                         unsigned b0, unsigned b1) {
    asm volatile(
        "mma.sync.aligned.m16n8k16.row.col.f32.f16.f16.f32 "
        "{%0,%1,%2,%3}, {%4,%5,%6,%7}, {%8,%9}, {%0,%1,%2,%3};"
        : "+f"(d[0]), "+f"(d[1]), "+f"(d[2]), "+f"(d[3])
        : "r"(a0), "r"(a1), "r"(a2), "r"(a3), "r"(b0), "r"(b1));
}

// ---------------------------------------------------------------------------
// Fused layer over degree-sorted node tiles: gather 32 nodes -> smem (scaled
// by nin), HMMA 32x64 @ 64x64, fused epilogue (scattered row writes).
//   LAYER==1: out = g_H2h (fp16), epi = relu(.)*nout
//   LAYER==2: out = out_param (fp32 d_out), epi = identity
template <int LAYER>
__global__ void __launch_bounds__(256)
k_fused(const int* __restrict__ src, const int* __restrict__ dst,
        const float* __restrict__ bias, float* __restrict__ out_param) {
    __shared__ __align__(16) __half sA[32 * 64];    // 4KB swizzled
    __shared__ __align__(16) __half sB[64 * 64];    // 8KB swizzled
    __shared__ float bs[64];
    __shared__ int   sperm[32];

    const int t = threadIdx.x;
    const int wid = t >> 5, lane = t & 31;
    const uint4* Hv = reinterpret_cast<const uint4*>(LAYER == 1 ? g_Hh : g_H2h);

    // B: pre-transposed fp16 weights -> swizzled smem (2x16B per thread)
    {
        const uint4* wt4 = reinterpret_cast<const uint4*>(g_Wt[LAYER - 1]);
        #pragma unroll
        for (int q = 0; q < 2; q++) {
            int idx = q * 256 + t;
            uint4 v = wt4[idx];
            *reinterpret_cast<uint4*>(
                reinterpret_cast<char*>(sB) + SW128(idx * 16)) = v;
        }
    }
    if (t < 64) bs[t] = bias[t];

    // ---- gather phase: 8 threads per node, thread j owns 16B chunk j ----
    {
        int local = t >> 3;
        int n = g_perm[blockIdx.x * 32 + local];   // degree-sorted tile
        int j = t & 7;
        if (j == 0) sperm[local] = n;
        int cnt = g_cnt[n];
        int lim = cnt < ADJ_STRIDE ? cnt : ADJ_STRIDE;
        const int* lst = &g_adj[n * ADJ_STRIDE];
        float4 accA = make_float4(0.f, 0.f, 0.f, 0.f);
        float4 accB = make_float4(0.f, 0.f, 0.f, 0.f);
        int k = 0;
        for (; k + 4 <= lim; k += 4) {
            int4 s4 = *reinterpret_cast<const int4*>(&lst[k]);
            uint4 u0 = Hv[s4.x * 8 + j];
            uint4 u1 = Hv[s4.y * 8 + j];
            uint4 u2 = Hv[s4.z * 8 + j];
            uint4 u3 = Hv[s4.w * 8 + j];
            acc8h(accA, accB, hadd2x4(hadd2x4(u0, u1), hadd2x4(u2, u3)));
        }
        for (; k + 2 <= lim; k += 2) {
            uint4 u0 = Hv[__ldg(&lst[k]) * 8 + j];
            uint4 u1 = Hv[__ldg(&lst[k + 1]) * 8 + j];
            acc8h(accA, accB, hadd2x4(u0, u1));
        }
        if (k < lim) acc8h(accA, accB, Hv[__ldg(&lst[k]) * 8 + j]);
        if (cnt > ADJ_STRIDE) {                 // overflow (expected none)
            int oc = g_ovf_cnt; if (oc > OVF_CAP) oc = OVF_CAP;
            for (int i = 0; i < oc; i++) {
                int e = g_ovf[i];
                if (dst[e] == n) acc8h(accA, accB, Hv[src[e] * 8 + j]);
            }
        }
        float s = g_nin[n];
        __half2 h0 = __floats2half2_rn(accA.x * s, accA.y * s);
        __half2 h1 = __floats2half2_rn(accA.z * s, accA.w * s);
        __half2 h2 = __floats2half2_rn(accB.x * s, accB.y * s);
        __half2 h3 = __floats2half2_rn(accB.z * s, accB.w * s);
        uint4 u;
        u.x = *reinterpret_cast<unsigned*>(&h0);
        u.y = *reinterpret_cast<unsigned*>(&h1);
        u.z = *reinterpret_cast<unsigned*>(&h2);
        u.w = *reinterpret_cast<unsigned*>(&h3);
        *reinterpret_cast<uint4*>(
            reinterpret_cast<char*>(sA) + SW128(local * 128 + j * 16)) = u;
    }
    __syncthreads();

    // ---- MMA phase: warp = (row-half i, col-group p) of 32x64 output ----
    const unsigned baseA = smem_u32(sA);
    const unsigned baseB = smem_u32(sB);
    const int i = wid >> 2;                 // 0..1 (16-row half)
    const int p = wid & 3;                  // 0..3 (16-col group)
    const int lrow = lane & 15;
    const int lcol = (lane >> 4) * 16;

    float d[2][4];
    #pragma unroll
    for (int jj = 0; jj < 2; jj++)
        #pragma unroll
        for (int q = 0; q < 4; q++) d[jj][q] = 0.f;

    #pragma unroll
    for (int kk = 0; kk < 4; kk++) {
        unsigned a0, a1, a2, a3;
        ldmx4(a0, a1, a2, a3,
              baseA + SW128((i * 16 + lrow) * 128 + kk * 32 + lcol));
        unsigned r0, r1, r2, r3;
        ldmx4(r0, r1, r2, r3,
              baseB + SW128((p * 16 + lrow) * 128 + kk * 32 + lcol));
        mma16816(d[0], a0, a1, a2, a3, r0, r2);
        mma16816(d[1], a0, a1, a2, a3, r1, r3);
    }

    // ---- epilogue: warp's 16x16 quadrant, scattered rows via sperm ----
    const int g   = lane >> 2;
    const int tid = lane & 3;
    #pragma unroll
    for (int jj = 0; jj < 2; jj++) {
        #pragma unroll
        for (int half = 0; half < 2; half++) {
            int row = sperm[i * 16 + g + half * 8];
            int c = p * 16 + jj * 8 + tid * 2;
            float v0 = d[jj][half * 2 + 0] + bs[c];
            float v1 = d[jj][half * 2 + 1] + bs[c + 1];
            if (LAYER == 1) {
                float no = g_nout[row];
                v0 = fmaxf(v0, 0.f) * no;
                v1 = fmaxf(v1, 0.f) * no;
                __half2 h = __floats2half2_rn(v0, v1);
                *reinterpret_cast<__half2*>(&g_H2h[row * DD + c]) = h;
            } else {
                *reinterpret_cast<float2*>(&out_param[row * DD + c]) =
                    make_float2(v0, v1);
            }
        }
    }
}

// ---------------------------------------------------------------------------
extern "C" void kernel_launch(void* const* d_in, const int* in_sizes, int n_in,
                              void* d_out, int out_size) {
    const float* feats = 0;
    const int *edgeA = 0, *edgeB = 0;
    const float* Wv[2] = {0, 0};
    const float* bv[2] = {0, 0};
    int wi = 0, bi = 0;
    for (int i = 0; i < n_in; i++) {
        int sz = in_sizes[i];
        if (sz == NN * DD)      feats = (const float*)d_in[i];
        else if (sz == NE)      { if (!edgeA) edgeA = (const int*)d_in[i]; else edgeB = (const int*)d_in[i]; }
        else if (sz == DD * DD) { if (wi < 2) Wv[wi++] = (const float*)d_in[i]; }
        else if (sz == DD)      { if (bi < 2) bv[bi++] = (const float*)d_in[i]; }
    }
    const int* src = edgeA;   // insertion order: src precedes dst (verified R4)
    const int* dst = edgeB;
    float* out = (float*)d_out;

    const int T = 256;
    const int g_nodes  = (NN + T - 1) / T;
    const int g_edges4 = (NE / 4 + T - 1) / T;
    const int g_scale4 = (NN * 4 + T - 1) / T;    // 4 float4 per thread

    k_zero <<<g_nodes,  T>>>(Wv[0], Wv[1]);       // counters+buckets+W transpose
    k_build<<<g_edges4, T>>>((const int4*)src, (const int4*)dst);
    k_norm <<<g_nodes,  T>>>();                   // norms + degree histogram
    k_scan <<<1, 32>>>();
    k_perm <<<g_nodes,  T>>>();
    k_scale<<<g_scale4, T>>>((const float4*)feats);

    k_fused<1><<<NTF, T>>>(src, dst, bv[0], 0);
    k_fused<2><<<NTF, T>>>(src, dst, bv[1], out);
}

// round 15
// speedup vs baseline: 1.1389x; 1.1389x over previous
#include <cuda_runtime.h>
#include <cuda_fp16.h>

#define NN 100000
#define NE 1200000
#define DD 64
#define ADJ_STRIDE 32
#define OVF_CAP 8192
#define NTF 3125                // 100000/32 fused tiles (exact)
#define SW128(o) ((o) ^ ((((o) >> 3)) & 0x70))

typedef unsigned long long u64;

// Scratch (device globals — no allocation allowed)
__device__ __half g_Hh  [NN * DD];        // layer-1 gather source (feats*nout)
__device__ __half g_H2h [NN * DD];        // layer-2 gather source
__device__ __half g_Wt[2][DD * DD];       // pre-transposed fp16 weights [c*64+k]
__device__ int   g_degout[NN];
__device__ int   g_cnt[NN];
__device__ float g_nout[NN];
__device__ float g_nin[NN];
__device__ int   g_adj[NN * ADJ_STRIDE];
__device__ int   g_ovf[OVF_CAP];
__device__ int   g_ovf_cnt;

// ---------------------------------------------------------------------------
// zero counters + pre-transpose weights (merged: saves a launch)
__global__ void k_zero(const float* __restrict__ W1, const float* __restrict__ W2) {
    int i = blockIdx.x * blockDim.x + threadIdx.x;
    if (i < NN) { g_degout[i] = 0; g_cnt[i] = 0; }
    if (i == 0) g_ovf_cnt = 0;
    if (i < 2 * DD * DD) {
        int l = i >> 12;
        int r = i & 4095;
        int c = r >> 6, k = r & 63;
        const float* W = l ? W2 : W1;
        g_Wt[l][c * 64 + k] = __float2half_rn(W[k * 64 + c]);
    }
}

// 4 edges per thread (int4 loads) for atomic-latency MLP.
__global__ void k_build(const int4* __restrict__ src4, const int4* __restrict__ dst4) {
    int e4 = blockIdx.x * blockDim.x + threadIdx.x;
    if (e4 >= NE / 4) return;
    int4 s = src4[e4];
    int4 d = dst4[e4];
    atomicAdd(&g_degout[s.x], 1);
    atomicAdd(&g_degout[s.y], 1);
    atomicAdd(&g_degout[s.z], 1);
    atomicAdd(&g_degout[s.w], 1);
    int c0 = atomicAdd(&g_cnt[d.x], 1);
    int c1 = atomicAdd(&g_cnt[d.y], 1);
    int c2 = atomicAdd(&g_cnt[d.z], 1);
    int c3 = atomicAdd(&g_cnt[d.w], 1);
    int base = e4 * 4;
    if (c0 < ADJ_STRIDE) g_adj[d.x * ADJ_STRIDE + c0] = s.x;
    else { int o = atomicAdd(&g_ovf_cnt, 1); if (o < OVF_CAP) g_ovf[o] = base; }
    if (c1 < ADJ_STRIDE) g_adj[d.y * ADJ_STRIDE + c1] = s.y;
    else { int o = atomicAdd(&g_ovf_cnt, 1); if (o < OVF_CAP) g_ovf[o] = base + 1; }
    if (c2 < ADJ_STRIDE) g_adj[d.z * ADJ_STRIDE + c2] = s.z;
    else { int o = atomicAdd(&g_ovf_cnt, 1); if (o < OVF_CAP) g_ovf[o] = base + 2; }
    if (c3 < ADJ_STRIDE) g_adj[d.w * ADJ_STRIDE + c3] = s.w;
    else { int o = atomicAdd(&g_ovf_cnt, 1); if (o < OVF_CAP) g_ovf[o] = base + 3; }
}

// Fused norms + scale: one thread per row.
//   nout/nin computed once per row (one rsqrt pair), persisted;
//   Hh[row] = half(feats[row] * nout[row])  (4x float4 -> 2x uint4)
__global__ void k_scale(const float4* __restrict__ feats) {
    int row = blockIdx.x * blockDim.x + threadIdx.x;
    if (row >= NN) return;
    float no = rsqrtf(fmaxf((float)g_degout[row], 1.0f));
    float ni = rsqrtf(fmaxf((float)g_cnt[row],  1.0f));
    g_nout[row] = no;
    g_nin[row]  = ni;
    int t0 = row * 16;
    float4 v0 = feats[t0];
    float4 v1 = feats[t0 + 1];
    float4 v2 = feats[t0 + 2];
    float4 v3 = feats[t0 + 3];
    float4 v4 = feats[t0 + 4];
    float4 v5 = feats[t0 + 5];
    float4 v6 = feats[t0 + 6];
    float4 v7 = feats[t0 + 7];
    float4 v8 = feats[t0 + 8];
    float4 v9 = feats[t0 + 9];
    float4 va = feats[t0 + 10];
    float4 vb = feats[t0 + 11];
    float4 vc = feats[t0 + 12];
    float4 vd = feats[t0 + 13];
    float4 ve = feats[t0 + 14];
    float4 vf = feats[t0 + 15];
    uint4* outp = reinterpret_cast<uint4*>(&g_Hh[row * DD]);
    #define PACK8(A, B, idx) do {                                   \
        __half2 h0 = __floats2half2_rn((A).x * no, (A).y * no);     \
        __half2 h1 = __floats2half2_rn((A).z * no, (A).w * no);     \
        __half2 h2 = __floats2half2_rn((B).x * no, (B).y * no);     \
        __half2 h3 = __floats2half2_rn((B).z * no, (B).w * no);     \
        uint4 uu;                                                    \
        uu.x = *reinterpret_cast<unsigned*>(&h0);                    \
        uu.y = *reinterpret_cast<unsigned*>(&h1);                    \
        uu.z = *reinterpret_cast<unsigned*>(&h2);                    \
        uu.w = *reinterpret_cast<unsigned*>(&h3);                    \
        outp[idx] = uu;                                              \
    } while (0)
    PACK8(v0, v1, 0); PACK8(v2, v3, 1); PACK8(v4, v5, 2); PACK8(v6, v7, 3);
    PACK8(v8, v9, 4); PACK8(va, vb, 5); PACK8(vc, vd, 6); PACK8(ve, vf, 7);
    #undef PACK8
}

// acc (8 floats) += 8 halves packed in uint4
__device__ __forceinline__ void acc8h(float4& a, float4& b, uint4 u) {
    float2 f0 = __half22float2(*reinterpret_cast<__half2*>(&u.x));
    float2 f1 = __half22float2(*reinterpret_cast<__half2*>(&u.y));
    float2 f2 = __half22float2(*reinterpret_cast<__half2*>(&u.z));
    float2 f3 = __half22float2(*reinterpret_cast<__half2*>(&u.w));
    a.x += f0.x; a.y += f0.y; a.z += f1.x; a.w += f1.y;
    b.x += f2.x; b.y += f2.y; b.z += f3.x; b.w += f3.y;
}
// pairwise fp16 add of two uint4s (4x HADD2)
__device__ __forceinline__ uint4 hadd2x4(uint4 a, uint4 b) {
    uint4 r;
    *reinterpret_cast<__half2*>(&r.x) = __hadd2(*reinterpret_cast<__half2*>(&a.x),
                                                *reinterpret_cast<__half2*>(&b.x));
    *reinterpret_cast<__half2*>(&r.y) = __hadd2(*reinterpret_cast<__half2*>(&a.y),
                                                *reinterpret_cast<__half2*>(&b.y));
    *reinterpret_cast<__half2*>(&r.z) = __hadd2(*reinterpret_cast<__half2*>(&a.z),
                                                *reinterpret_cast<__half2*>(&b.z));
    *reinterpret_cast<__half2*>(&r.w) = __hadd2(*reinterpret_cast<__half2*>(&a.w),
                                                *reinterpret_cast<__half2*>(&b.w));
    return r;
}

__device__ __forceinline__ unsigned smem_u32(const void* p) {
    unsigned a;
    asm("{ .reg .u64 t; cvta.to.shared.u64 t, %1; cvt.u32.u64 %0, t; }" : "=r"(a) : "l"(p));
    return a;
}
__device__ __forceinline__ void ldmx4(unsigned& r0, unsigned& r1, unsigned& r2,
                                      unsigned& r3, unsigned addr) {
    asm volatile("ldmatrix.sync.aligned.m8n8.x4.shared.b16 {%0,%1,%2,%3}, [%4];"
                 : "=r"(r0), "=r"(r1), "=r"(r2), "=r"(r3) : "r"(addr));
}
__device__ __forceinline__ void mma16816(float* d, unsigned a0, unsigned a1,
                                         unsigned a2, unsigned a3,
                                         unsigned b0, unsigned b1) {
    asm volatile(
        "mma.sync.aligned.m16n8k16.row.col.f32.f16.f16.f32 "
        "{%0,%1,%2,%3}, {%4,%5,%6,%7}, {%8,%9}, {%0,%1,%2,%3};"
        : "+f"(d[0]), "+f"(d[1]), "+f"(d[2]), "+f"(d[3])
        : "r"(a0), "r"(a1), "r"(a2), "r"(a3), "r"(b0), "r"(b1));
}

// ---------------------------------------------------------------------------
// Fused layer: gather 32 contiguous nodes -> smem (scaled by nin),
// HMMA 32x64 @ 64x64, fused epilogue. (R13 winner — contiguous tiles.)
//   LAYER==1: out = g_H2h (fp16), epi = relu(.)*nout
//   LAYER==2: out = out_param (fp32 d_out), epi = identity
template <int LAYER>
__global__ void __launch_bounds__(256)
k_fused(const int* __restrict__ src, const int* __restrict__ dst,
        const float* __restrict__ bias, float* __restrict__ out_param) {
    __shared__ __align__(16) __half sA[32 * 64];    // 4KB swizzled
    __shared__ __align__(16) __half sB[64 * 64];    // 8KB swizzled
    __shared__ float bs[64];

    const int t = threadIdx.x;
    const int wid = t >> 5, lane = t & 31;
    const uint4* Hv = reinterpret_cast<const uint4*>(LAYER == 1 ? g_Hh : g_H2h);

    // B: pre-transposed fp16 weights -> swizzled smem (2x16B per thread)
    {
        const uint4* wt4 = reinterpret_cast<const uint4*>(g_Wt[LAYER - 1]);
        #pragma unroll
        for (int q = 0; q < 2; q++) {
            int idx = q * 256 + t;
            uint4 v = wt4[idx];
            *reinterpret_cast<uint4*>(
                reinterpret_cast<char*>(sB) + SW128(idx * 16)) = v;
        }
    }
    if (t < 64) bs[t] = bias[t];

    // ---- gather phase: 8 threads per node, thread j owns 16B chunk j ----
    {
        int n = blockIdx.x * 32 + (t >> 3);     // NTF*32 == NN exactly
        int j = t & 7;
        int cnt = g_cnt[n];
        int lim = cnt < ADJ_STRIDE ? cnt : ADJ_STRIDE;
        const int* lst = &g_adj[n * ADJ_STRIDE];
        float4 accA = make_float4(0.f, 0.f, 0.f, 0.f);
        float4 accB = make_float4(0.f, 0.f, 0.f, 0.f);
        int k = 0;
        for (; k + 4 <= lim; k += 4) {
            int4 s4 = *reinterpret_cast<const int4*>(&lst[k]);
            uint4 u0 = Hv[s4.x * 8 + j];
            uint4 u1 = Hv[s4.y * 8 + j];
            uint4 u2 = Hv[s4.z * 8 + j];
            uint4 u3 = Hv[s4.w * 8 + j];
            acc8h(accA, accB, hadd2x4(hadd2x4(u0, u1), hadd2x4(u2, u3)));
        }
        for (; k + 2 <= lim; k += 2) {
            uint4 u0 = Hv[__ldg(&lst[k]) * 8 + j];
            uint4 u1 = Hv[__ldg(&lst[k + 1]) * 8 + j];
            acc8h(accA, accB, hadd2x4(u0, u1));
        }
        if (k < lim) acc8h(accA, accB, Hv[__ldg(&lst[k]) * 8 + j]);
        if (cnt > ADJ_STRIDE) {                 // overflow (expected none)
            int oc = g_ovf_cnt; if (oc > OVF_CAP) oc = OVF_CAP;
            for (int i = 0; i < oc; i++) {
                int e = g_ovf[i];
                if (dst[e] == n) acc8h(accA, accB, Hv[src[e] * 8 + j]);
            }
        }
        float s = g_nin[n];
        __half2 h0 = __floats2half2_rn(accA.x * s, accA.y * s);
        __half2 h1 = __floats2half2_rn(accA.z * s, accA.w * s);
        __half2 h2 = __floats2half2_rn(accB.x * s, accB.y * s);
        __half2 h3 = __floats2half2_rn(accB.z * s, accB.w * s);
        uint4 u;
        u.x = *reinterpret_cast<unsigned*>(&h0);
        u.y = *reinterpret_cast<unsigned*>(&h1);
        u.z = *reinterpret_cast<unsigned*>(&h2);
        u.w = *reinterpret_cast<unsigned*>(&h3);
        *reinterpret_cast<uint4*>(
            reinterpret_cast<char*>(sA) + SW128((t >> 3) * 128 + j * 16)) = u;
    }
    __syncthreads();

    // ---- MMA phase: warp = (row-half i, col-group p) of 32x64 output ----
    const unsigned baseA = smem_u32(sA);
    const unsigned baseB = smem_u32(sB);
    const int i = wid >> 2;                 // 0..1 (16-row half)
    const int p = wid & 3;                  // 0..3 (16-col group)
    const int lrow = lane & 15;
    const int lcol = (lane >> 4) * 16;

    float d[2][4];
    #pragma unroll
    for (int jj = 0; jj < 2; jj++)
        #pragma unroll
        for (int q = 0; q < 4; q++) d[jj][q] = 0.f;

    #pragma unroll
    for (int kk = 0; kk < 4; kk++) {
        unsigned a0, a1, a2, a3;
        ldmx4(a0, a1, a2, a3,
              baseA + SW128((i * 16 + lrow) * 128 + kk * 32 + lcol));
        unsigned r0, r1, r2, r3;
        ldmx4(r0, r1, r2, r3,
              baseB + SW128((p * 16 + lrow) * 128 + kk * 32 + lcol));
        mma16816(d[0], a0, a1, a2, a3, r0, r2);
        mma16816(d[1], a0, a1, a2, a3, r1, r3);
    }

    // ---- epilogue: warp's 16x16 quadrant (contiguous rows) ----
    const int g   = lane >> 2;
    const int tid = lane & 3;
    #pragma unroll
    for (int jj = 0; jj < 2; jj++) {
        #pragma unroll
        for (int half = 0; half < 2; half++) {
            int row = blockIdx.x * 32 + i * 16 + g + half * 8;
            int c = p * 16 + jj * 8 + tid * 2;
            float v0 = d[jj][half * 2 + 0] + bs[c];
            float v1 = d[jj][half * 2 + 1] + bs[c + 1];
            if (LAYER == 1) {
                float no = g_nout[row];
                v0 = fmaxf(v0, 0.f) * no;
                v1 = fmaxf(v1, 0.f) * no;
                __half2 h = __floats2half2_rn(v0, v1);
                *reinterpret_cast<__half2*>(&g_H2h[row * DD + c]) = h;
            } else {
                *reinterpret_cast<float2*>(&out_param[row * DD + c]) =
                    make_float2(v0, v1);
            }
        }
    }
}

// ---------------------------------------------------------------------------
extern "C" void kernel_launch(void* const* d_in, const int* in_sizes, int n_in,
                              void* d_out, int out_size) {
    const float* feats = 0;
    const int *edgeA = 0, *edgeB = 0;
    const float* Wv[2] = {0, 0};
    const float* bv[2] = {0, 0};
    int wi = 0, bi = 0;
    for (int i = 0; i < n_in; i++) {
        int sz = in_sizes[i];
        if (sz == NN * DD)      feats = (const float*)d_in[i];
        else if (sz == NE)      { if (!edgeA) edgeA = (const int*)d_in[i]; else edgeB = (const int*)d_in[i]; }
        else if (sz == DD * DD) { if (wi < 2) Wv[wi++] = (const float*)d_in[i]; }
        else if (sz == DD)      { if (bi < 2) bv[bi++] = (const float*)d_in[i]; }
    }
    const int* src = edgeA;   // insertion order: src precedes dst (verified R4)
    const int* dst = edgeB;
    float* out = (float*)d_out;

    const int T = 256;
    const int g_nodes  = (NN + T - 1) / T;
    const int g_edges4 = (NE / 4 + T - 1) / T;

    k_zero <<<g_nodes,  T>>>(Wv[0], Wv[1]);       // counters + W transpose
    k_build<<<g_edges4, T>>>((const int4*)src, (const int4*)dst);
    k_scale<<<g_nodes,  T>>>((const float4*)feats);  // norms + H (1 row/thread)

    k_fused<1><<<NTF, T>>>(src, dst, bv[0], 0);
    k_fused<2><<<NTF, T>>>(src, dst, bv[1], out);
}